// round 1
// baseline (speedup 1.0000x reference)
#include <cuda_runtime.h>
#include <cstdint>

#define BATCH 64
#define SEQ   1024
#define DIN   256
#define UNITS 512

// ============================ Scan configuration ============================
// Grid: NUC x NBC = 16 x 8 = 128 CTAs (one wave on 148 SMs, co-resident).
// CTA tile: TB=8 batches x TU=32 units. 128 threads = 4 warps.
// Warp w handles batches {2w, 2w+1}; lane = local unit index (0..31).
#define TB 8
#define TU 32
#define NBC (BATCH / TB)   // 8
#define NUC (UNITS / TU)   // 16
#define NCTAS (NBC * NUC)  // 128
#define SCAN_THREADS 128

// U slice in smem, transposed [u][k] with padded stride for conflict-free LDS.128
#define UKPAD 516  // 512 + 4

// Ping-pong hidden state buffers + grid barrier state (allocation-free scratch)
__device__ float    g_H[2][BATCH * UNITS];
__device__ unsigned g_bar_count = 0;
__device__ unsigned g_bar_gen   = 0;

__device__ __forceinline__ void grid_barrier() {
    __syncthreads();
    if (threadIdx.x == 0) {
        unsigned gen = *((volatile unsigned*)&g_bar_gen);
        __threadfence();
        unsigned arrived = atomicAdd(&g_bar_count, 1u);
        if (arrived == NCTAS - 1) {
            g_bar_count = 0;
            __threadfence();
            *((volatile unsigned*)&g_bar_gen) = gen + 1u;
        } else {
            while (*((volatile unsigned*)&g_bar_gen) == gen) { }
        }
        __threadfence();
    }
    __syncthreads();
}

// ============================ Phase 2: LTC scan =============================
// out holds G = inv_tau*(xW + b) on entry; overwritten in place with h_t.
__global__ void __launch_bounds__(SCAN_THREADS, 1)
ltc_scan(const float* __restrict__ Umat,
         const float* __restrict__ tau,
         float* __restrict__ out)
{
    const int ju   = blockIdx.x;            // unit tile 0..15
    const int ib   = blockIdx.y;            // batch tile 0..7
    const int tid  = threadIdx.x;
    const int lane = tid & 31;
    const int w    = tid >> 5;              // warp 0..3
    const int b0   = 2 * w;                 // local batches
    const int b1   = 2 * w + 1;
    const int ug   = ju * TU + lane;        // global unit index

    extern __shared__ float smem[];
    float* Us = smem;                        // [TU][UKPAD] = 32 x 516 floats
    float* Hs = smem + TU * UKPAD;           // [TB][UNITS] = 8 x 512 floats

    // ---- Load U slice transposed: Us[u_local][k] = U[k][ju*TU + u_local] ----
    {
        const float4* Ug4 = reinterpret_cast<const float4*>(Umat);
        for (int i = tid; i < UNITS * (TU / 4); i += SCAN_THREADS) {
            int k = i / (TU / 4);
            int g = i % (TU / 4);
            float4 v = Ug4[k * (UNITS / 4) + ju * (TU / 4) + g];
            int ub = g * 4;
            Us[(ub + 0) * UKPAD + k] = v.x;
            Us[(ub + 1) * UKPAD + k] = v.y;
            Us[(ub + 2) * UKPAD + k] = v.z;
            Us[(ub + 3) * UKPAD + k] = v.w;
        }
    }

    const float it = 1.0f / tau[ug];
    const float aa = 1.0f - it;

    // ---- Zero-init h0 for this CTA's (batch, unit) tile ----
    {
        int bgA = ib * TB + b0;
        int bgB = ib * TB + b1;
        __stcg(&g_H[0][bgA * UNITS + ug], 0.0f);
        __stcg(&g_H[0][bgB * UNITS + ug], 0.0f);
    }
    __threadfence();
    grid_barrier();

    const float* UsRow = &Us[lane * UKPAD];
    int cur = 0;

    for (int t = 0; t < SEQ; t++) {
        // ---- Load H[cur] rows for this batch tile into smem (L2-coherent) ----
        {
            const float4* Hg4 = reinterpret_cast<const float4*>(&g_H[cur][(ib * TB) * UNITS]);
            float4* Hs4 = reinterpret_cast<float4*>(Hs);
            #pragma unroll
            for (int i = 0; i < (TB * UNITS / 4) / SCAN_THREADS; i++)
                Hs4[i * SCAN_THREADS + tid] = __ldcg(&Hg4[i * SCAN_THREADS + tid]);
        }
        __syncthreads();

        // ---- h_prev @ U for 2 batches, unit = ug ----
        float acc00 = 0.f, acc01 = 0.f, acc10 = 0.f, acc11 = 0.f;
        {
            const float4* H0 = reinterpret_cast<const float4*>(&Hs[b0 * UNITS]);
            const float4* H1 = reinterpret_cast<const float4*>(&Hs[b1 * UNITS]);
            const float4* U4 = reinterpret_cast<const float4*>(UsRow);
            #pragma unroll 8
            for (int q = 0; q < UNITS / 8; q++) {
                float4 u0 = U4[2 * q + 0];
                float4 u1 = U4[2 * q + 1];
                float4 ha0 = H0[2 * q + 0];
                float4 ha1 = H0[2 * q + 1];
                float4 hb0 = H1[2 * q + 0];
                float4 hb1 = H1[2 * q + 1];
                acc00 += ha0.x * u0.x + ha0.y * u0.y + ha0.z * u0.z + ha0.w * u0.w;
                acc01 += ha1.x * u1.x + ha1.y * u1.y + ha1.z * u1.z + ha1.w * u1.w;
                acc10 += hb0.x * u0.x + hb0.y * u0.y + hb0.z * u0.z + hb0.w * u0.w;
                acc11 += hb1.x * u1.x + hb1.y * u1.y + hb1.z * u1.z + hb1.w * u1.w;
            }
        }
        float accA = acc00 + acc01;
        float accB = acc10 + acc11;

        // ---- Epilogue: h_new = (1-it)*h_prev + G_t + it*(hU) ----
        {
            int bgA = ib * TB + b0;
            int bgB = ib * TB + b1;
            size_t oA = ((size_t)bgA * SEQ + t) * UNITS + ug;
            size_t oB = ((size_t)bgB * SEQ + t) * UNITS + ug;
            float gA = __ldcg(&out[oA]);
            float gB = __ldcg(&out[oB]);
            float hpA = Hs[b0 * UNITS + ug];
            float hpB = Hs[b1 * UNITS + ug];
            float hnA = aa * hpA + gA + it * accA;
            float hnB = aa * hpB + gB + it * accB;
            out[oA] = hnA;
            out[oB] = hnB;
            int nxt = cur ^ 1;
            __stcg(&g_H[nxt][bgA * UNITS + ug], hnA);
            __stcg(&g_H[nxt][bgB * UNITS + ug], hnB);
        }
        __threadfence();
        grid_barrier();
        cur ^= 1;
    }
}

// ===================== Phase 1: G = inv_tau * (x@W + b) =====================
#define GBM 64
#define GBN 64
#define GBK 16

__global__ void __launch_bounds__(256)
ltc_gemm(const float* __restrict__ X,
         const float* __restrict__ Wm,
         const float* __restrict__ bias,
         const float* __restrict__ tau,
         float* __restrict__ G)
{
    __shared__ float As[GBK][GBM + 4];
    __shared__ float Bs[GBK][GBN];

    const int tid = threadIdx.x;
    const int bx = blockIdx.x;   // n tile 0..7
    const int by = blockIdx.y;   // m tile 0..1023

    const int arow = tid >> 2, akq = tid & 3;     // A load: 64 rows x 4 f4
    const int bkr  = tid >> 4, bnq = tid & 15;    // B load: 16 rows x 16 f4
    const int ty   = tid >> 4, tx  = tid & 15;    // compute 16x16, 4x4 micro

    float acc[4][4];
    #pragma unroll
    for (int i = 0; i < 4; i++)
        #pragma unroll
        for (int j = 0; j < 4; j++) acc[i][j] = 0.f;

    const size_t arow_g = (size_t)(by * GBM + arow) * DIN;

    for (int k0 = 0; k0 < DIN; k0 += GBK) {
        float4 av = *reinterpret_cast<const float4*>(&X[arow_g + k0 + akq * 4]);
        As[akq * 4 + 0][arow] = av.x;
        As[akq * 4 + 1][arow] = av.y;
        As[akq * 4 + 2][arow] = av.z;
        As[akq * 4 + 3][arow] = av.w;
        float4 bv = *reinterpret_cast<const float4*>(&Wm[(size_t)(k0 + bkr) * UNITS + bx * GBN + bnq * 4]);
        *reinterpret_cast<float4*>(&Bs[bkr][bnq * 4]) = bv;
        __syncthreads();

        #pragma unroll
        for (int k = 0; k < GBK; k++) {
            float4 am = *reinterpret_cast<const float4*>(&As[k][ty * 4]);
            float4 bn = *reinterpret_cast<const float4*>(&Bs[k][tx * 4]);
            float a0 = am.x, a1 = am.y, a2 = am.z, a3 = am.w;
            acc[0][0] += a0 * bn.x; acc[0][1] += a0 * bn.y; acc[0][2] += a0 * bn.z; acc[0][3] += a0 * bn.w;
            acc[1][0] += a1 * bn.x; acc[1][1] += a1 * bn.y; acc[1][2] += a1 * bn.z; acc[1][3] += a1 * bn.w;
            acc[2][0] += a2 * bn.x; acc[2][1] += a2 * bn.y; acc[2][2] += a2 * bn.z; acc[2][3] += a2 * bn.w;
            acc[3][0] += a3 * bn.x; acc[3][1] += a3 * bn.y; acc[3][2] += a3 * bn.z; acc[3][3] += a3 * bn.w;
        }
        __syncthreads();
    }

    // Epilogue: G = inv_tau * (acc + b)
    const int n0 = bx * GBN + tx * 4;
    float it0 = 1.0f / tau[n0 + 0], it1 = 1.0f / tau[n0 + 1];
    float it2 = 1.0f / tau[n0 + 2], it3 = 1.0f / tau[n0 + 3];
    float bb0 = bias[n0 + 0], bb1 = bias[n0 + 1], bb2 = bias[n0 + 2], bb3 = bias[n0 + 3];

    #pragma unroll
    for (int i = 0; i < 4; i++) {
        int m = by * GBM + ty * 4 + i;
        float4 v;
        v.x = it0 * (acc[i][0] + bb0);
        v.y = it1 * (acc[i][1] + bb1);
        v.z = it2 * (acc[i][2] + bb2);
        v.w = it3 * (acc[i][3] + bb3);
        *reinterpret_cast<float4*>(&G[(size_t)m * UNITS + n0]) = v;
    }
}

// ================================ Launcher ==================================
extern "C" void kernel_launch(void* const* d_in, const int* in_sizes, int n_in,
                              void* d_out, int out_size)
{
    const float* x   = (const float*)d_in[0];   // [64,1024,256]
    const float* Wm  = (const float*)d_in[1];   // [256,512]
    const float* Um  = (const float*)d_in[2];   // [512,512]
    const float* bb  = (const float*)d_in[3];   // [512]
    const float* tau = (const float*)d_in[4];   // [512]
    float* out = (float*)d_out;                 // [64,1024,512]

    (void)in_sizes; (void)n_in; (void)out_size;

    // Phase 1: G = inv_tau * (x@W + b) -> out
    dim3 ggrid(UNITS / GBN, (BATCH * SEQ) / GBM);  // (8, 1024)
    ltc_gemm<<<ggrid, 256>>>(x, Wm, bb, tau, out);

    // Phase 2: sequential scan (persistent, grid-barriered)
    const int smem_bytes = (TU * UKPAD + TB * UNITS) * (int)sizeof(float); // 82432
    cudaFuncSetAttribute(ltc_scan, cudaFuncAttributeMaxDynamicSharedMemorySize, smem_bytes);
    dim3 sgrid(NUC, NBC);  // (16, 8) = 128 CTAs
    ltc_scan<<<sgrid, SCAN_THREADS, smem_bytes>>>(Um, tau, out);
}

// round 2
// speedup vs baseline: 1.3341x; 1.3341x over previous
#include <cuda_runtime.h>
#include <cstdint>

#define BATCH 64
#define SEQ   1024
#define DIN   256
#define UNITS 512

// ============================ Scan configuration ============================
// Grid: 16 unit-tiles x 8 batch-tiles = 128 CTAs, 512 threads (16 warps) each.
// lane = local unit (32 units per CTA); warp w owns k-chunk [32w, 32w+32).
// U slice lives in REGISTERS as duplicated f32x2 pairs. H exchanged via L2
// within 16-CTA batch groups (independent per-group barriers).
#define TB 8
#define TU 32
#define NBC (BATCH / TB)    // 8 batch groups
#define NUC (UNITS / TU)    // 16 CTAs per group
#define SCAN_THREADS 512
#define NW 16               // warps per CTA
#define KCH (UNITS / NW)    // 32 k per warp
#define HS_STRIDE 12        // floats per unit row in smem (8 batches + pad), 3u mod 8 conflict-free
#define RED_STRIDE 9        // per-lane stride in reduction scratch (odd -> conflict-free)

__device__ float    g_H[2][BATCH * UNITS];
__device__ unsigned g_cnt[NBC * 32];   // per-group barrier counter (padded lines)
__device__ unsigned g_gen[NBC * 32];   // per-group generation flag

// packed fp32x2 FMA (2x fp32 rate on sm_103a; ptxas never auto-emits this)
#define FMA2(acc, h, u) asm("fma.rn.f32x2 %0, %1, %2, %0;" : "+l"(acc) : "l"(h), "l"(u))

__device__ __forceinline__ unsigned long long dup_f32(float v) {
    unsigned long long r;
    asm("mov.b64 %0, {%1, %1};" : "=l"(r) : "f"(v));
    return r;
}
__device__ __forceinline__ void unpack2(unsigned long long v, float& lo, float& hi) {
    asm("mov.b64 {%0, %1}, %2;" : "=f"(lo), "=f"(hi) : "l"(v));
}

// Barrier among the 16 CTAs of one batch group.
__device__ __forceinline__ void group_barrier(int ib) {
    __threadfence();          // make this thread's H stores visible GPU-wide
    __syncthreads();          // all threads' fences done before leader arrives
    if (threadIdx.x == 0) {
        volatile unsigned* gen = &g_gen[ib * 32];
        unsigned g = *gen;
        unsigned arr = atomicAdd(&g_cnt[ib * 32], 1u);
        if (arr == NUC - 1) {
            g_cnt[ib * 32] = 0;
            __threadfence();
            *gen = g + 1u;
        } else {
            while (*gen == g) { }
        }
        __threadfence();      // acquire
    }
    __syncthreads();
}

// ============================ Phase 2: LTC scan =============================
// out holds G = inv_tau*(xW + b) on entry; overwritten in place with h_t.
__global__ void __launch_bounds__(SCAN_THREADS, 1)
ltc_scan(const float* __restrict__ Umat,
         const float* __restrict__ tau,
         float* __restrict__ out)
{
    const int ju   = blockIdx.x;            // unit tile 0..15
    const int ib   = blockIdx.y;            // batch tile 0..7
    const int tid  = threadIdx.x;
    const int lane = tid & 31;
    const int w    = tid >> 5;              // warp 0..15 (also epilogue batch for tid<256)
    const int u    = ju * TU + lane;        // global unit index
    const int kb   = w * KCH;               // this warp's k base
    const int bg0  = ib * TB;               // first global batch of this group

    __shared__ float Hs[UNITS * HS_STRIDE];           // 24576 B: Hs[k][b] (b fast, padded)
    __shared__ float Red[NW * 32 * RED_STRIDE];       // 18432 B: Red[w][lane][b]

    // ---- U slice into registers, duplicated pairs: UU[i] = (U[kb+i][u], same) ----
    unsigned long long UU[KCH];
    #pragma unroll
    for (int i = 0; i < KCH; i++)
        UU[i] = dup_f32(Umat[(size_t)(kb + i) * UNITS + u]);

    const float it = 1.0f / tau[u];
    const float aa = 1.0f - it;

    // ---- h0 = 0 (epilogue threads own one (b, u) pair each) ----
    if (tid < 256)
        __stcg(&g_H[0][(bg0 + w) * UNITS + u], 0.0f);
    group_barrier(ib);

    int cur = 0;
    for (int t = 0; t < SEQ; t++) {
        // ---- Exchange: thread tid gathers unit-row tid across the 8 batches ----
        {
            float h[8];
            #pragma unroll
            for (int b = 0; b < 8; b++)
                h[b] = __ldcg(&g_H[cur][(bg0 + b) * UNITS + tid]);
            float4* dst = reinterpret_cast<float4*>(&Hs[tid * HS_STRIDE]);
            dst[0] = make_float4(h[0], h[1], h[2], h[3]);
            dst[1] = make_float4(h[4], h[5], h[6], h[7]);
        }
        __syncthreads();

        // ---- Partial dot: this warp's 32-k chunk, all 8 batches, unit=lane ----
        unsigned long long a0 = 0, a1 = 0, a2 = 0, a3 = 0;
        #pragma unroll
        for (int i = 0; i < KCH; i++) {
            const ulonglong2* hv = reinterpret_cast<const ulonglong2*>(&Hs[(kb + i) * HS_STRIDE]);
            ulonglong2 hA = hv[0];   // (h[b0],h[b1]) , (h[b2],h[b3])  -- broadcast LDS
            ulonglong2 hB = hv[1];   // (h[b4],h[b5]) , (h[b6],h[b7])
            FMA2(a0, hA.x, UU[i]);
            FMA2(a1, hA.y, UU[i]);
            FMA2(a2, hB.x, UU[i]);
            FMA2(a3, hB.y, UU[i]);
        }

        // ---- Spill partials: Red[w][lane][b] ----
        {
            float* r = &Red[(w * 32 + lane) * RED_STRIDE];
            float x0, x1; unpack2(a0, x0, x1); r[0] = x0; r[1] = x1;
            float x2, x3; unpack2(a1, x2, x3); r[2] = x2; r[3] = x3;
            float x4, x5; unpack2(a2, x4, x5); r[4] = x4; r[5] = x5;
            float x6, x7; unpack2(a3, x6, x7); r[6] = x6; r[7] = x7;
        }
        __syncthreads();

        // ---- Reduce over 16 warps + epilogue (256 threads: b=w, unit=lane) ----
        if (tid < 256) {
            float s = 0.0f;
            #pragma unroll
            for (int ww = 0; ww < NW; ww++)
                s += Red[(ww * 32 + lane) * RED_STRIDE + w];

            float hp = Hs[u * HS_STRIDE + w];
            size_t o = ((size_t)(bg0 + w) * SEQ + t) * UNITS + u;
            float g  = __ldcg(&out[o]);
            float hn = aa * hp + g + it * s;
            out[o] = hn;
            __stcg(&g_H[cur ^ 1][(bg0 + w) * UNITS + u], hn);
        }
        group_barrier(ib);
        cur ^= 1;
    }
}

// ===================== Phase 1: G = inv_tau * (x@W + b) =====================
#define GBM 64
#define GBN 64
#define GBK 16

__global__ void __launch_bounds__(256)
ltc_gemm(const float* __restrict__ X,
         const float* __restrict__ Wm,
         const float* __restrict__ bias,
         const float* __restrict__ tau,
         float* __restrict__ G)
{
    __shared__ float As[GBK][GBM + 4];
    __shared__ float Bs[GBK][GBN];

    const int tid = threadIdx.x;
    const int bx = blockIdx.x;   // n tile 0..7
    const int by = blockIdx.y;   // m tile 0..1023

    const int arow = tid >> 2, akq = tid & 3;     // A load: 64 rows x 4 f4
    const int bkr  = tid >> 4, bnq = tid & 15;    // B load: 16 rows x 16 f4
    const int ty   = tid >> 4, tx  = tid & 15;    // compute 16x16, 4x4 micro

    unsigned long long acc[4][2];                 // packed (n,n+1) f32x2 pairs
    #pragma unroll
    for (int i = 0; i < 4; i++) { acc[i][0] = 0ull; acc[i][1] = 0ull; }

    const size_t arow_g = (size_t)(by * GBM + arow) * DIN;

    for (int k0 = 0; k0 < DIN; k0 += GBK) {
        float4 av = *reinterpret_cast<const float4*>(&X[arow_g + k0 + akq * 4]);
        As[akq * 4 + 0][arow] = av.x;
        As[akq * 4 + 1][arow] = av.y;
        As[akq * 4 + 2][arow] = av.z;
        As[akq * 4 + 3][arow] = av.w;
        float4 bv = *reinterpret_cast<const float4*>(&Wm[(size_t)(k0 + bkr) * UNITS + bx * GBN + bnq * 4]);
        *reinterpret_cast<float4*>(&Bs[bkr][bnq * 4]) = bv;
        __syncthreads();

        #pragma unroll
        for (int k = 0; k < GBK; k++) {
            float4 am = *reinterpret_cast<const float4*>(&As[k][ty * 4]);
            ulonglong2 bn = *reinterpret_cast<const ulonglong2*>(&Bs[k][tx * 4]);
            unsigned long long a0 = dup_f32(am.x);
            unsigned long long a1 = dup_f32(am.y);
            unsigned long long a2 = dup_f32(am.z);
            unsigned long long a3 = dup_f32(am.w);
            FMA2(acc[0][0], bn.x, a0); FMA2(acc[0][1], bn.y, a0);
            FMA2(acc[1][0], bn.x, a1); FMA2(acc[1][1], bn.y, a1);
            FMA2(acc[2][0], bn.x, a2); FMA2(acc[2][1], bn.y, a2);
            FMA2(acc[3][0], bn.x, a3); FMA2(acc[3][1], bn.y, a3);
        }
        __syncthreads();
    }

    // Epilogue: G = inv_tau * (acc + b)
    const int n0 = bx * GBN + tx * 4;
    float it0 = 1.0f / tau[n0 + 0], it1 = 1.0f / tau[n0 + 1];
    float it2 = 1.0f / tau[n0 + 2], it3 = 1.0f / tau[n0 + 3];
    float bb0 = bias[n0 + 0], bb1 = bias[n0 + 1], bb2 = bias[n0 + 2], bb3 = bias[n0 + 3];

    #pragma unroll
    for (int i = 0; i < 4; i++) {
        int m = by * GBM + ty * 4 + i;
        float c0, c1, c2, c3;
        unpack2(acc[i][0], c0, c1);
        unpack2(acc[i][1], c2, c3);
        float4 v;
        v.x = it0 * (c0 + bb0);
        v.y = it1 * (c1 + bb1);
        v.z = it2 * (c2 + bb2);
        v.w = it3 * (c3 + bb3);
        *reinterpret_cast<float4*>(&G[(size_t)m * UNITS + n0]) = v;
    }
}

// ================================ Launcher ==================================
extern "C" void kernel_launch(void* const* d_in, const int* in_sizes, int n_in,
                              void* d_out, int out_size)
{
    const float* x   = (const float*)d_in[0];   // [64,1024,256]
    const float* Wm  = (const float*)d_in[1];   // [256,512]
    const float* Um  = (const float*)d_in[2];   // [512,512]
    const float* bb  = (const float*)d_in[3];   // [512]
    const float* tau = (const float*)d_in[4];   // [512]
    float* out = (float*)d_out;                 // [64,1024,512]

    (void)in_sizes; (void)n_in; (void)out_size;

    // Phase 1: G = inv_tau * (x@W + b) -> out
    dim3 ggrid(UNITS / GBN, (BATCH * SEQ) / GBM);  // (8, 1024)
    ltc_gemm<<<ggrid, 256>>>(x, Wm, bb, tau, out);

    // Phase 2: sequential scan (persistent, per-group barriers)
    dim3 sgrid(NUC, NBC);  // (16, 8) = 128 CTAs
    ltc_scan<<<sgrid, SCAN_THREADS>>>(Um, tau, out);
}

// round 5
// speedup vs baseline: 2.4070x; 1.8042x over previous
#include <cuda_runtime.h>
#include <cstdint>

#define BATCH 64
#define SEQ   1024
#define DIN   256
#define UNITS 512

// ============================ Scan configuration ============================
// Grid: 16 unit-tiles x 8 batch-tiles = 128 CTAs, 512 threads (16 warps).
// lane = local unit; warp w owns k-chunk [32w, 32w+32). U slice in REGISTERS
// as duplicated f32x2 pairs. H exchanged through L2 as self-validating
// (value, tag) 64-bit words accessed with MORALLY-STRONG relaxed GPU-scope
// atomics (single-copy atomic -> no tag/value tearing), no barriers/fences.
// Tag buffers zeroed by ltc_clear each call (cross-replay hygiene).
#define TB 8
#define TU 32
#define NBC (BATCH / TB)    // 8 batch groups
#define NUC (UNITS / TU)    // 16 CTAs per group
#define SCAN_THREADS 512
#define NW 16               // warps per CTA
#define KCH (UNITS / NW)    // 32 k per warp
#define HS_STRIDE 12        // floats per unit row in smem (8 batches + pad)
#define RED_STRIDE 9        // per-lane stride in reduction scratch

// Ping-pong tagged hidden state: word = (tag << 32) | float_bits(h)
__device__ unsigned long long g_Hx[2][BATCH * UNITS];

// packed fp32x2 FMA (2x fp32 rate on sm_103a; ptxas never auto-emits this)
#define FMA2(acc, h, u) asm("fma.rn.f32x2 %0, %1, %2, %0;" : "+l"(acc) : "l"(h), "l"(u))

__device__ __forceinline__ unsigned long long dup_f32(float v) {
    unsigned long long r;
    asm("mov.b64 %0, {%1, %1};" : "=l"(r) : "f"(v));
    return r;
}
__device__ __forceinline__ void unpack2(unsigned long long v, float& lo, float& hi) {
    asm("mov.b64 {%0, %1}, %2;" : "=f"(lo), "=f"(hi) : "l"(v));
}
// Morally-strong relaxed GPU-scope 64-bit load: single-copy atomic, L2 point.
__device__ __forceinline__ unsigned long long ld_poll(const unsigned long long* p) {
    unsigned long long v;
    asm volatile("ld.relaxed.gpu.global.b64 %0, [%1];" : "=l"(v) : "l"(p));
    return v;
}
__device__ __forceinline__ void st_tagged(unsigned long long* p, float h, unsigned tag) {
    unsigned long long v = ((unsigned long long)tag << 32) | (unsigned long long)__float_as_uint(h);
    asm volatile("st.relaxed.gpu.global.b64 [%0], %1;" :: "l"(p), "l"(v));
}

// ====================== Phase 1.5: clear tag buffers ========================
__global__ void ltc_clear()
{
    unsigned long long* p = &g_Hx[0][0];
    int i = blockIdx.x * blockDim.x + threadIdx.x;
    const int total = 2 * BATCH * UNITS;
    for (; i < total; i += gridDim.x * blockDim.x)
        p[i] = 0ull;
}

// ============================ Phase 2: LTC scan =============================
// out holds G = inv_tau*(xW + b) on entry; overwritten in place with h_t.
__global__ void __launch_bounds__(SCAN_THREADS, 1)
ltc_scan(const float* __restrict__ Umat,
         const float* __restrict__ tau,
         float* __restrict__ out)
{
    const int ju   = blockIdx.x;            // unit tile 0..15
    const int ib   = blockIdx.y;            // batch tile 0..7
    const int tid  = threadIdx.x;
    const int lane = tid & 31;
    const int w    = tid >> 5;              // warp 0..15 (= epilogue batch for tid<256)
    const int u    = ju * TU + lane;        // global unit index
    const int kb   = w * KCH;               // this warp's k base
    const int bg0  = ib * TB;               // first global batch of this group

    __shared__ float Hs[UNITS * HS_STRIDE];      // Hs[k][b], b fast, padded
    __shared__ float Red[NW * 32 * RED_STRIDE];  // Red[w][lane][b]

    // ---- U slice into registers, duplicated pairs: UU[i] = (U[kb+i][u], dup) ----
    unsigned long long UU[KCH];
    #pragma unroll
    for (int i = 0; i < KCH; i++)
        UU[i] = dup_f32(Umat[(size_t)(kb + i) * UNITS + u]);

    const float it = 1.0f / tau[u];
    const float aa = 1.0f - it;

    // ---- h0 = 0, tag 1 (owners store; consumers poll for tag 1) ----
    if (tid < 256)
        st_tagged(&g_Hx[0][(bg0 + w) * UNITS + u], 0.0f, 1u);

    int cur = 0;
    for (int t = 0; t < SEQ; t++) {
        const unsigned want = (unsigned)(t + 1);

        // ---- Prefetch this step's G early (overlaps the poll below) ----
        float gt = 0.0f;
        size_t o = 0;
        if (tid < 256) {
            o = ((size_t)(bg0 + w) * SEQ + t) * UNITS + u;
            gt = out[o];
        }

        // ---- Poll exchange: thread tid gathers unit-row `tid` for 8 batches ----
        unsigned long long v[8];
        {
            const unsigned long long* src = &g_Hx[cur][tid];
            bool ok;
            do {
                ok = true;
                #pragma unroll
                for (int b = 0; b < 8; b++)
                    v[b] = ld_poll(&src[(size_t)(bg0 + b) * UNITS]);
                #pragma unroll
                for (int b = 0; b < 8; b++)
                    ok &= ((unsigned)(v[b] >> 32) == want);
            } while (!ok);
        }
        // ---- Stage into smem: Hs[tid][0..7] ----
        {
            float4* dst = reinterpret_cast<float4*>(&Hs[tid * HS_STRIDE]);
            dst[0] = make_float4(__uint_as_float((unsigned)v[0]), __uint_as_float((unsigned)v[1]),
                                 __uint_as_float((unsigned)v[2]), __uint_as_float((unsigned)v[3]));
            dst[1] = make_float4(__uint_as_float((unsigned)v[4]), __uint_as_float((unsigned)v[5]),
                                 __uint_as_float((unsigned)v[6]), __uint_as_float((unsigned)v[7]));
        }
        __syncthreads();

        // ---- Partial dot: this warp's 32-k chunk, all 8 batches, unit=lane ----
        unsigned long long a0 = 0, a1 = 0, a2 = 0, a3 = 0;
        #pragma unroll
        for (int i = 0; i < KCH; i++) {
            const ulonglong2* hv = reinterpret_cast<const ulonglong2*>(&Hs[(kb + i) * HS_STRIDE]);
            ulonglong2 hA = hv[0];   // broadcast LDS.128: (b0,b1),(b2,b3)
            ulonglong2 hB = hv[1];   // (b4,b5),(b6,b7)
            FMA2(a0, hA.x, UU[i]);
            FMA2(a1, hA.y, UU[i]);
            FMA2(a2, hB.x, UU[i]);
            FMA2(a3, hB.y, UU[i]);
        }

        // ---- h_prev for epilogue (read Hs BEFORE it can be restaged) ----
        float hp = 0.0f;
        if (tid < 256) hp = Hs[u * HS_STRIDE + w];

        // ---- Spill partials: Red[w][lane][b] ----
        {
            float* r = &Red[(w * 32 + lane) * RED_STRIDE];
            float x0, x1; unpack2(a0, x0, x1); r[0] = x0; r[1] = x1;
            float x2, x3; unpack2(a1, x2, x3); r[2] = x2; r[3] = x3;
            float x4, x5; unpack2(a2, x4, x5); r[4] = x4; r[5] = x5;
            float x6, x7; unpack2(a3, x6, x7); r[6] = x6; r[7] = x7;
        }
        __syncthreads();

        // ---- Reduce over 16 warps + epilogue (256 threads: b=w, unit=lane) ----
        if (tid < 256) {
            float s = 0.0f;
            #pragma unroll
            for (int ww = 0; ww < NW; ww++)
                s += Red[(ww * 32 + lane) * RED_STRIDE + w];

            float hn = aa * hp + gt + it * s;
            out[o] = hn;
            st_tagged(&g_Hx[cur ^ 1][(bg0 + w) * UNITS + u], hn, (unsigned)(t + 2));
        }
        cur ^= 1;
        // No third sync needed: next iteration's Hs/Red writes are gated by the
        // second sync above plus the poll (which requires every group producer's
        // step to be fully finished, which requires all their polls done).
    }
}

// ===================== Phase 1: G = inv_tau * (x@W + b) =====================
#define GBM 64
#define GBN 64
#define GBK 16

__global__ void __launch_bounds__(256)
ltc_gemm(const float* __restrict__ X,
         const float* __restrict__ Wm,
         const float* __restrict__ bias,
         const float* __restrict__ tau,
         float* __restrict__ G)
{
    __shared__ float As[GBK][GBM + 4];
    __shared__ float Bs[GBK][GBN];

    const int tid = threadIdx.x;
    const int bx = blockIdx.x;   // n tile 0..7
    const int by = blockIdx.y;   // m tile 0..1023

    const int arow = tid >> 2, akq = tid & 3;
    const int bkr  = tid >> 4, bnq = tid & 15;
    const int ty   = tid >> 4, tx  = tid & 15;

    unsigned long long acc[4][2];
    #pragma unroll
    for (int i = 0; i < 4; i++) { acc[i][0] = 0ull; acc[i][1] = 0ull; }

    const size_t arow_g = (size_t)(by * GBM + arow) * DIN;

    for (int k0 = 0; k0 < DIN; k0 += GBK) {
        float4 av = *reinterpret_cast<const float4*>(&X[arow_g + k0 + akq * 4]);
        As[akq * 4 + 0][arow] = av.x;
        As[akq * 4 + 1][arow] = av.y;
        As[akq * 4 + 2][arow] = av.z;
        As[akq * 4 + 3][arow] = av.w;
        float4 bv = *reinterpret_cast<const float4*>(&Wm[(size_t)(k0 + bkr) * UNITS + bx * GBN + bnq * 4]);
        *reinterpret_cast<float4*>(&Bs[bkr][bnq * 4]) = bv;
        __syncthreads();

        #pragma unroll
        for (int k = 0; k < GBK; k++) {
            float4 am = *reinterpret_cast<const float4*>(&As[k][ty * 4]);
            ulonglong2 bn = *reinterpret_cast<const ulonglong2*>(&Bs[k][tx * 4]);
            unsigned long long a0 = dup_f32(am.x);
            unsigned long long a1 = dup_f32(am.y);
            unsigned long long a2 = dup_f32(am.z);
            unsigned long long a3 = dup_f32(am.w);
            FMA2(acc[0][0], bn.x, a0); FMA2(acc[0][1], bn.y, a0);
            FMA2(acc[1][0], bn.x, a1); FMA2(acc[1][1], bn.y, a1);
            FMA2(acc[2][0], bn.x, a2); FMA2(acc[2][1], bn.y, a2);
            FMA2(acc[3][0], bn.x, a3); FMA2(acc[3][1], bn.y, a3);
        }
        __syncthreads();
    }

    const int n0 = bx * GBN + tx * 4;
    float it0 = 1.0f / tau[n0 + 0], it1 = 1.0f / tau[n0 + 1];
    float it2 = 1.0f / tau[n0 + 2], it3 = 1.0f / tau[n0 + 3];
    float bb0 = bias[n0 + 0], bb1 = bias[n0 + 1], bb2 = bias[n0 + 2], bb3 = bias[n0 + 3];

    #pragma unroll
    for (int i = 0; i < 4; i++) {
        int m = by * GBM + ty * 4 + i;
        float c0, c1, c2, c3;
        unpack2(acc[i][0], c0, c1);
        unpack2(acc[i][1], c2, c3);
        float4 v;
        v.x = it0 * (c0 + bb0);
        v.y = it1 * (c1 + bb1);
        v.z = it2 * (c2 + bb2);
        v.w = it3 * (c3 + bb3);
        *reinterpret_cast<float4*>(&G[(size_t)m * UNITS + n0]) = v;
    }
}

// ================================ Launcher ==================================
extern "C" void kernel_launch(void* const* d_in, const int* in_sizes, int n_in,
                              void* d_out, int out_size)
{
    const float* x   = (const float*)d_in[0];   // [64,1024,256]
    const float* Wm  = (const float*)d_in[1];   // [256,512]
    const float* Um  = (const float*)d_in[2];   // [512,512]
    const float* bb  = (const float*)d_in[3];   // [512]
    const float* tau = (const float*)d_in[4];   // [512]
    float* out = (float*)d_out;                 // [64,1024,512]

    (void)in_sizes; (void)n_in; (void)out_size;

    // Clear tag buffers (cross-replay hygiene)
    ltc_clear<<<128, 256>>>();

    // Phase 1: G = inv_tau * (x@W + b) -> out
    dim3 ggrid(UNITS / GBN, (BATCH * SEQ) / GBM);  // (8, 1024)
    ltc_gemm<<<ggrid, 256>>>(x, Wm, bb, tau, out);

    // Phase 2: sequential scan (tagged ping-pong exchange, barrier-free,
    // relaxed GPU-scope atomics)
    dim3 sgrid(NUC, NBC);  // (16, 8) = 128 CTAs
    ltc_scan<<<sgrid, SCAN_THREADS>>>(Um, tau, out);
}

// round 6
// speedup vs baseline: 2.7639x; 1.1482x over previous
#include <cuda_runtime.h>
#include <cstdint>

#define BATCH 64
#define SEQ   1024
#define DIN   256
#define UNITS 512
#define NROUND (SEQ / 2)    // 512 two-step rounds

// ============================ Scan configuration ============================
#define TB 8
#define TU 32
#define NBC (BATCH / TB)    // 8 batch groups
#define NUC (UNITS / TU)    // 16 CTAs per group
#define SCAN_THREADS 512
#define NW 16               // warps per CTA
#define KCH (UNITS / NW)    // 32 k per warp
#define HS_STRIDE 12
#define RED_STRIDE 9

// Ping-pong tagged hidden state: word = (tag << 32) | float_bits(h)
__device__ unsigned long long g_Hx[2][BATCH * UNITS];
// Combined transition matrices and precomputed 2-step input term
__device__ float g_A [UNITS * UNITS];                 // A  = diag(1-it) + U*diag(it)
__device__ float g_A2[UNITS * UNITS];                 // A^2
__device__ float g_Gam[BATCH * NROUND * UNITS];       // Gam[b][r][u] = (g_{2r} A + g_{2r+1})  (67MB)

// packed fp32x2 FMA (2x fp32 rate on sm_103a; ptxas never auto-emits this)
#define FMA2(acc, h, u) asm("fma.rn.f32x2 %0, %1, %2, %0;" : "+l"(acc) : "l"(h), "l"(u))

__device__ __forceinline__ unsigned long long dup_f32(float v) {
    unsigned long long r;
    asm("mov.b64 %0, {%1, %1};" : "=l"(r) : "f"(v));
    return r;
}
__device__ __forceinline__ void unpack2(unsigned long long v, float& lo, float& hi) {
    asm("mov.b64 {%0, %1}, %2;" : "=f"(lo), "=f"(hi) : "l"(v));
}
// Morally-strong relaxed GPU-scope 64-bit ops: single-copy atomic, L2 point.
__device__ __forceinline__ unsigned long long ld_poll(const unsigned long long* p) {
    unsigned long long v;
    asm volatile("ld.relaxed.gpu.global.b64 %0, [%1];" : "=l"(v) : "l"(p));
    return v;
}
__device__ __forceinline__ void st_tagged(unsigned long long* p, float h, unsigned tag) {
    unsigned long long v = ((unsigned long long)tag << 32) | (unsigned long long)__float_as_uint(h);
    asm volatile("st.relaxed.gpu.global.b64 [%0], %1;" :: "l"(p), "l"(v));
}

// ====================== clear tag buffers (cross-replay) ====================
__global__ void ltc_clear()
{
    unsigned long long* p = &g_Hx[0][0];
    int i = blockIdx.x * blockDim.x + threadIdx.x;
    const int total = 2 * BATCH * UNITS;
    for (; i < total; i += gridDim.x * blockDim.x)
        p[i] = 0ull;
}

// ====================== build A = diag(1-it) + U*diag(it) ===================
__global__ void build_A(const float* __restrict__ U, const float* __restrict__ tau)
{
    int u = threadIdx.x;
    int k = blockIdx.x;
    float it = 1.0f / tau[u];
    float v = U[k * UNITS + u] * it;
    if (k == u) v += 1.0f - it;
    g_A[k * UNITS + u] = v;
}

// =============================== A2 = A @ A =================================
#define GBM 64
#define GBN 64
#define GBK 16

__global__ void __launch_bounds__(256)
gemm_A2()
{
    __shared__ float As[GBK][GBM + 4];
    __shared__ float Bs[GBK][GBN];

    const int tid = threadIdx.x;
    const int bx = blockIdx.x, by = blockIdx.y;
    const int arow = tid >> 2, akq = tid & 3;
    const int bkr  = tid >> 4, bnq = tid & 15;
    const int ty   = tid >> 4, tx  = tid & 15;

    unsigned long long acc[4][2];
    #pragma unroll
    for (int i = 0; i < 4; i++) { acc[i][0] = 0ull; acc[i][1] = 0ull; }

    const size_t arow_g = (size_t)(by * GBM + arow) * UNITS;

    for (int k0 = 0; k0 < UNITS; k0 += GBK) {
        float4 av = *reinterpret_cast<const float4*>(&g_A[arow_g + k0 + akq * 4]);
        As[akq * 4 + 0][arow] = av.x;
        As[akq * 4 + 1][arow] = av.y;
        As[akq * 4 + 2][arow] = av.z;
        As[akq * 4 + 3][arow] = av.w;
        float4 bv = *reinterpret_cast<const float4*>(&g_A[(size_t)(k0 + bkr) * UNITS + bx * GBN + bnq * 4]);
        *reinterpret_cast<float4*>(&Bs[bkr][bnq * 4]) = bv;
        __syncthreads();
        #pragma unroll
        for (int k = 0; k < GBK; k++) {
            float4 am = *reinterpret_cast<const float4*>(&As[k][ty * 4]);
            ulonglong2 bn = *reinterpret_cast<const ulonglong2*>(&Bs[k][tx * 4]);
            unsigned long long a0 = dup_f32(am.x), a1 = dup_f32(am.y);
            unsigned long long a2 = dup_f32(am.z), a3 = dup_f32(am.w);
            FMA2(acc[0][0], bn.x, a0); FMA2(acc[0][1], bn.y, a0);
            FMA2(acc[1][0], bn.x, a1); FMA2(acc[1][1], bn.y, a1);
            FMA2(acc[2][0], bn.x, a2); FMA2(acc[2][1], bn.y, a2);
            FMA2(acc[3][0], bn.x, a3); FMA2(acc[3][1], bn.y, a3);
        }
        __syncthreads();
    }
    const int n0 = bx * GBN + tx * 4;
    #pragma unroll
    for (int i = 0; i < 4; i++) {
        int m = by * GBM + ty * 4 + i;
        float c0, c1, c2, c3;
        unpack2(acc[i][0], c0, c1);
        unpack2(acc[i][1], c2, c3);
        *reinterpret_cast<float4*>(&g_A2[(size_t)m * UNITS + n0]) = make_float4(c0, c1, c2, c3);
    }
}

// ===================== Phase 1: G = inv_tau * (x@W + b) =====================
__global__ void __launch_bounds__(256)
ltc_gemm(const float* __restrict__ X,
         const float* __restrict__ Wm,
         const float* __restrict__ bias,
         const float* __restrict__ tau,
         float* __restrict__ G)
{
    __shared__ float As[GBK][GBM + 4];
    __shared__ float Bs[GBK][GBN];

    const int tid = threadIdx.x;
    const int bx = blockIdx.x, by = blockIdx.y;
    const int arow = tid >> 2, akq = tid & 3;
    const int bkr  = tid >> 4, bnq = tid & 15;
    const int ty   = tid >> 4, tx  = tid & 15;

    unsigned long long acc[4][2];
    #pragma unroll
    for (int i = 0; i < 4; i++) { acc[i][0] = 0ull; acc[i][1] = 0ull; }

    const size_t arow_g = (size_t)(by * GBM + arow) * DIN;

    for (int k0 = 0; k0 < DIN; k0 += GBK) {
        float4 av = *reinterpret_cast<const float4*>(&X[arow_g + k0 + akq * 4]);
        As[akq * 4 + 0][arow] = av.x;
        As[akq * 4 + 1][arow] = av.y;
        As[akq * 4 + 2][arow] = av.z;
        As[akq * 4 + 3][arow] = av.w;
        float4 bv = *reinterpret_cast<const float4*>(&Wm[(size_t)(k0 + bkr) * UNITS + bx * GBN + bnq * 4]);
        *reinterpret_cast<float4*>(&Bs[bkr][bnq * 4]) = bv;
        __syncthreads();
        #pragma unroll
        for (int k = 0; k < GBK; k++) {
            float4 am = *reinterpret_cast<const float4*>(&As[k][ty * 4]);
            ulonglong2 bn = *reinterpret_cast<const ulonglong2*>(&Bs[k][tx * 4]);
            unsigned long long a0 = dup_f32(am.x), a1 = dup_f32(am.y);
            unsigned long long a2 = dup_f32(am.z), a3 = dup_f32(am.w);
            FMA2(acc[0][0], bn.x, a0); FMA2(acc[0][1], bn.y, a0);
            FMA2(acc[1][0], bn.x, a1); FMA2(acc[1][1], bn.y, a1);
            FMA2(acc[2][0], bn.x, a2); FMA2(acc[2][1], bn.y, a2);
            FMA2(acc[3][0], bn.x, a3); FMA2(acc[3][1], bn.y, a3);
        }
        __syncthreads();
    }

    const int n0 = bx * GBN + tx * 4;
    float it0 = 1.0f / tau[n0 + 0], it1 = 1.0f / tau[n0 + 1];
    float it2 = 1.0f / tau[n0 + 2], it3 = 1.0f / tau[n0 + 3];
    float bb0 = bias[n0 + 0], bb1 = bias[n0 + 1], bb2 = bias[n0 + 2], bb3 = bias[n0 + 3];

    #pragma unroll
    for (int i = 0; i < 4; i++) {
        int m = by * GBM + ty * 4 + i;
        float c0, c1, c2, c3;
        unpack2(acc[i][0], c0, c1);
        unpack2(acc[i][1], c2, c3);
        float4 v;
        v.x = it0 * (c0 + bb0);
        v.y = it1 * (c1 + bb1);
        v.z = it2 * (c2 + bb2);
        v.w = it3 * (c3 + bb3);
        *reinterpret_cast<float4*>(&G[(size_t)m * UNITS + n0]) = v;
    }
}

// ============== Gamma prep: Gam[b][r] = G[b][2r]*A + G[b][2r+1] =============
// M = 64*512 rows (m = b*512 + r), K = 512, N = 512.
__global__ void __launch_bounds__(256)
gemm_gam(const float* __restrict__ G)
{
    __shared__ float As[GBK][GBM + 4];
    __shared__ float Bs[GBK][GBN];

    const int tid = threadIdx.x;
    const int bx = blockIdx.x, by = blockIdx.y;   // bx: n tile 0..7, by: m tile 0..511
    const int arow = tid >> 2, akq = tid & 3;
    const int bkr  = tid >> 4, bnq = tid & 15;
    const int ty   = tid >> 4, tx  = tid & 15;

    const int bglob = by >> 3;            // batch (64 rows per tile, 512 rows per batch)
    const int r0    = (by & 7) * GBM;     // first round index in tile

    unsigned long long acc[4][2];
    #pragma unroll
    for (int i = 0; i < 4; i++) { acc[i][0] = 0ull; acc[i][1] = 0ull; }

    // source row for A-operand: G[b][2*(r0+arow)][:]
    const size_t arow_g = ((size_t)bglob * SEQ + 2 * (r0 + arow)) * UNITS;

    for (int k0 = 0; k0 < UNITS; k0 += GBK) {
        float4 av = *reinterpret_cast<const float4*>(&G[arow_g + k0 + akq * 4]);
        As[akq * 4 + 0][arow] = av.x;
        As[akq * 4 + 1][arow] = av.y;
        As[akq * 4 + 2][arow] = av.z;
        As[akq * 4 + 3][arow] = av.w;
        float4 bv = *reinterpret_cast<const float4*>(&g_A[(size_t)(k0 + bkr) * UNITS + bx * GBN + bnq * 4]);
        *reinterpret_cast<float4*>(&Bs[bkr][bnq * 4]) = bv;
        __syncthreads();
        #pragma unroll
        for (int k = 0; k < GBK; k++) {
            float4 am = *reinterpret_cast<const float4*>(&As[k][ty * 4]);
            ulonglong2 bn = *reinterpret_cast<const ulonglong2*>(&Bs[k][tx * 4]);
            unsigned long long a0 = dup_f32(am.x), a1 = dup_f32(am.y);
            unsigned long long a2 = dup_f32(am.z), a3 = dup_f32(am.w);
            FMA2(acc[0][0], bn.x, a0); FMA2(acc[0][1], bn.y, a0);
            FMA2(acc[1][0], bn.x, a1); FMA2(acc[1][1], bn.y, a1);
            FMA2(acc[2][0], bn.x, a2); FMA2(acc[2][1], bn.y, a2);
            FMA2(acc[3][0], bn.x, a3); FMA2(acc[3][1], bn.y, a3);
        }
        __syncthreads();
    }

    const int n0 = bx * GBN + tx * 4;
    #pragma unroll
    for (int i = 0; i < 4; i++) {
        int r = r0 + ty * 4 + i;
        float c0, c1, c2, c3;
        unpack2(acc[i][0], c0, c1);
        unpack2(acc[i][1], c2, c3);
        // add g_{2r+1}
        float4 go = *reinterpret_cast<const float4*>(&G[((size_t)bglob * SEQ + 2 * r + 1) * UNITS + n0]);
        float4 v = make_float4(c0 + go.x, c1 + go.y, c2 + go.z, c3 + go.w);
        *reinterpret_cast<float4*>(&g_Gam[((size_t)bglob * NROUND + r) * UNITS + n0]) = v;
    }
}

// ============================ Phase 2: LTC scan =============================
// Per round r (2 timesteps): y_even = h*A + g_{2r}; h_next = h*A2 + Gam_r.
// out holds G on entry; overwritten in place with h_t.
__global__ void __launch_bounds__(SCAN_THREADS, 1)
ltc_scan(float* __restrict__ out)
{
    const int ju   = blockIdx.x;            // unit tile 0..15
    const int ib   = blockIdx.y;            // batch tile 0..7
    const int tid  = threadIdx.x;
    const int lane = tid & 31;
    const int w    = tid >> 5;              // warp 0..15 (= epilogue batch for tid<256)
    const int u    = ju * TU + lane;        // global unit index
    const int kb   = w * KCH;               // this warp's k base
    const int bg0  = ib * TB;               // first global batch of this group

    extern __shared__ float smem[];
    float* A2s  = smem;                              // [512][32] scalar A2 slice (64KB)
    float* Hs   = A2s + UNITS * TU;                  // [512][HS_STRIDE]
    float* Red1 = Hs + UNITS * HS_STRIDE;            // [16][32][RED_STRIDE]
    float* Red2 = Red1 + NW * 32 * RED_STRIDE;

    // ---- A slice into registers (duplicated pairs): UU[i] = dup(A[kb+i][u]) ----
    unsigned long long UU[KCH];
    #pragma unroll
    for (int i = 0; i < KCH; i++)
        UU[i] = dup_f32(g_A[(size_t)(kb + i) * UNITS + u]);

    // ---- A2 slice into smem: A2s[k][ul] = A2[k][ju*32+ul] ----
    for (int idx = tid; idx < UNITS * TU; idx += SCAN_THREADS) {
        int k = idx >> 5, ul = idx & 31;
        A2s[idx] = g_A2[(size_t)k * UNITS + ju * TU + ul];
    }

    // ---- h0 = 0, tag 1 ----
    if (tid < 256)
        st_tagged(&g_Hx[0][(bg0 + w) * UNITS + u], 0.0f, 1u);

    int cur = 0;
    for (int r = 0; r < NROUND; r++) {
        const unsigned want = (unsigned)(r + 1);

        // ---- Prefetch g_{2r} and Gam_r (overlap the poll) ----
        float gt = 0.0f, gam = 0.0f;
        size_t o = 0;
        if (tid < 256) {
            o   = ((size_t)(bg0 + w) * SEQ + 2 * r) * UNITS + u;
            gt  = out[o];
            gam = g_Gam[((size_t)(bg0 + w) * NROUND + r) * UNITS + u];
        }

        // ---- Poll exchange: thread tid gathers unit-row `tid` for 8 batches ----
        unsigned long long v[8];
        {
            const unsigned long long* src = &g_Hx[cur][tid];
            bool ok;
            do {
                ok = true;
                #pragma unroll
                for (int b = 0; b < 8; b++)
                    v[b] = ld_poll(&src[(size_t)(bg0 + b) * UNITS]);
                #pragma unroll
                for (int b = 0; b < 8; b++)
                    ok &= ((unsigned)(v[b] >> 32) == want);
            } while (!ok);
        }
        // ---- Stage into smem: Hs[tid][0..7] ----
        {
            float4* dst = reinterpret_cast<float4*>(&Hs[tid * HS_STRIDE]);
            dst[0] = make_float4(__uint_as_float((unsigned)v[0]), __uint_as_float((unsigned)v[1]),
                                 __uint_as_float((unsigned)v[2]), __uint_as_float((unsigned)v[3]));
            dst[1] = make_float4(__uint_as_float((unsigned)v[4]), __uint_as_float((unsigned)v[5]),
                                 __uint_as_float((unsigned)v[6]), __uint_as_float((unsigned)v[7]));
        }
        __syncthreads();

        // ---- Dual partial dots: h*A (regs) and h*A2 (smem), 8 batches ----
        unsigned long long a0 = 0, a1 = 0, a2 = 0, a3 = 0;
        unsigned long long c0 = 0, c1 = 0, c2 = 0, c3 = 0;
        #pragma unroll
        for (int i = 0; i < KCH; i++) {
            const ulonglong2* hv = reinterpret_cast<const ulonglong2*>(&Hs[(kb + i) * HS_STRIDE]);
            ulonglong2 hA = hv[0];
            ulonglong2 hB = hv[1];
            unsigned long long u2 = dup_f32(A2s[(kb + i) * TU + lane]);
            FMA2(a0, hA.x, UU[i]);
            FMA2(a1, hA.y, UU[i]);
            FMA2(a2, hB.x, UU[i]);
            FMA2(a3, hB.y, UU[i]);
            FMA2(c0, hA.x, u2);
            FMA2(c1, hA.y, u2);
            FMA2(c2, hB.x, u2);
            FMA2(c3, hB.y, u2);
        }

        // ---- Spill partials ----
        {
            float* r1 = &Red1[(w * 32 + lane) * RED_STRIDE];
            float* r2 = &Red2[(w * 32 + lane) * RED_STRIDE];
            float x0, x1;
            unpack2(a0, x0, x1); r1[0] = x0; r1[1] = x1;
            unpack2(a1, x0, x1); r1[2] = x0; r1[3] = x1;
            unpack2(a2, x0, x1); r1[4] = x0; r1[5] = x1;
            unpack2(a3, x0, x1); r1[6] = x0; r1[7] = x1;
            unpack2(c0, x0, x1); r2[0] = x0; r2[1] = x1;
            unpack2(c1, x0, x1); r2[2] = x0; r2[3] = x1;
            unpack2(c2, x0, x1); r2[4] = x0; r2[5] = x1;
            unpack2(c3, x0, x1); r2[6] = x0; r2[7] = x1;
        }
        __syncthreads();

        // ---- Reduce + epilogue (256 threads: b=w, unit=lane) ----
        if (tid < 256) {
            float s1 = 0.0f, s2 = 0.0f;
            #pragma unroll
            for (int ww = 0; ww < NW; ww++) {
                s1 += Red1[(ww * 32 + lane) * RED_STRIDE + w];
                s2 += Red2[(ww * 32 + lane) * RED_STRIDE + w];
            }
            float y  = s1 + gt;    // h_{2r+1}, goes to out[2r]
            float hn = s2 + gam;   // h_{2r+2}, goes to out[2r+1] and next state
            out[o] = y;
            out[o + UNITS] = hn;
            st_tagged(&g_Hx[cur ^ 1][(bg0 + w) * UNITS + u], hn, (unsigned)(r + 2));
        }
        cur ^= 1;
    }
}

// ================================ Launcher ==================================
extern "C" void kernel_launch(void* const* d_in, const int* in_sizes, int n_in,
                              void* d_out, int out_size)
{
    const float* x   = (const float*)d_in[0];   // [64,1024,256]
    const float* Wm  = (const float*)d_in[1];   // [256,512]
    const float* Um  = (const float*)d_in[2];   // [512,512]
    const float* bb  = (const float*)d_in[3];   // [512]
    const float* tau = (const float*)d_in[4];   // [512]
    float* out = (float*)d_out;                 // [64,1024,512]

    (void)in_sizes; (void)n_in; (void)out_size;

    // Tag hygiene (cross-replay)
    ltc_clear<<<128, 256>>>();

    // A = diag(1-it) + U*diag(it);  A2 = A@A
    build_A<<<UNITS, UNITS>>>(Um, tau);
    gemm_A2<<<dim3(UNITS / GBN, UNITS / GBM), 256>>>();

    // G = inv_tau * (x@W + b) -> out
    ltc_gemm<<<dim3(UNITS / GBN, (BATCH * SEQ) / GBM), 256>>>(x, Wm, bb, tau, out);

    // Gam[b][r] = G[b][2r]*A + G[b][2r+1]
    gemm_gam<<<dim3(UNITS / GBN, (BATCH * NROUND) / GBM), 256>>>(out);

    // Two-step scan
    const int smem_bytes = (UNITS * TU + UNITS * HS_STRIDE + 2 * NW * 32 * RED_STRIDE) * (int)sizeof(float);
    cudaFuncSetAttribute(ltc_scan, cudaFuncAttributeMaxDynamicSharedMemorySize, smem_bytes);
    ltc_scan<<<dim3(NUC, NBC), SCAN_THREADS, smem_bytes>>>(out);
}